// round 1
// baseline (speedup 1.0000x reference)
#include <cuda_runtime.h>
#include <math.h>

#define B_  4
#define S_  2048
#define H_  1024
#define NH_ 16
#define HD_ 64
#define QKV_ELEMS (B_*NH_*S_*HD_)   // 8,388,608 floats = 32 MB each

// Scratch (no cudaMalloc allowed): Q/K/V in split-head layout [B, NH, S, HD]
__device__ float g_q[QKV_ELEMS];
__device__ float g_k[QKV_ELEMS];
__device__ float g_v[QKV_ELEMS];

// ---------------------------------------------------------------------------
// Kernel 1: fused QKV projection.  out[m,n] = sum_k X[m,k] * W[n,k] + bias[n]
// M=8192 (b*S+s), per-matrix N=1024, K=1024. Grid.y selects (matrix, n-block).
// Writes directly into split-head layout.
// ---------------------------------------------------------------------------
__global__ __launch_bounds__(256)
void qkv_proj(const float* __restrict__ X,
              const float* __restrict__ Wq, const float* __restrict__ bq,
              const float* __restrict__ Wk, const float* __restrict__ bk,
              const float* __restrict__ Wv, const float* __restrict__ bv)
{
    __shared__ float As[8][128];
    __shared__ float Bs[8][128];

    const int m0 = blockIdx.x * 128;
    const int nb = blockIdx.y;            // 0..23
    const int sel = nb >> 3;              // 0=Q 1=K 2=V
    const int n0  = (nb & 7) * 128;       // within-matrix n offset

    const float* __restrict__ W    = (sel == 0) ? Wq : (sel == 1) ? Wk : Wv;
    const float* __restrict__ bias = (sel == 0) ? bq : (sel == 1) ? bk : bv;
    float* __restrict__ out        = (sel == 0) ? g_q : (sel == 1) ? g_k : g_v;

    const int tid  = threadIdx.x;
    const int lrow = tid >> 1;            // 0..127
    const int lk4  = (tid & 1) * 4;       // 0 or 4

    const int tm = (tid >> 4) * 8;        // 0..120
    const int tn = (tid & 15) * 8;        // 0..120

    float acc[8][8];
#pragma unroll
    for (int i = 0; i < 8; i++)
#pragma unroll
        for (int j = 0; j < 8; j++) acc[i][j] = 0.f;

    const float* aptr = &X[(size_t)(m0 + lrow) * 1024 + lk4];
    const float* bptr = &W[(size_t)(n0 + lrow) * 1024 + lk4];

    for (int k0 = 0; k0 < 1024; k0 += 8) {
        float4 av = *(const float4*)(aptr + k0);
        float4 bv4 = *(const float4*)(bptr + k0);
        As[lk4 + 0][lrow] = av.x;  As[lk4 + 1][lrow] = av.y;
        As[lk4 + 2][lrow] = av.z;  As[lk4 + 3][lrow] = av.w;
        Bs[lk4 + 0][lrow] = bv4.x; Bs[lk4 + 1][lrow] = bv4.y;
        Bs[lk4 + 2][lrow] = bv4.z; Bs[lk4 + 3][lrow] = bv4.w;
        __syncthreads();

#pragma unroll
        for (int kk = 0; kk < 8; kk++) {
            float a[8], b[8];
#pragma unroll
            for (int i = 0; i < 8; i++) a[i] = As[kk][tm + i];
#pragma unroll
            for (int j = 0; j < 8; j++) b[j] = Bs[kk][tn + j];
#pragma unroll
            for (int i = 0; i < 8; i++)
#pragma unroll
                for (int j = 0; j < 8; j++)
                    acc[i][j] += a[i] * b[j];
        }
        __syncthreads();
    }

    // Epilogue: add bias, scatter into [B, NH, S, HD]
#pragma unroll
    for (int i = 0; i < 8; i++) {
        const int m = m0 + tm + i;
        const int bb = m / S_;
        const int ss = m % S_;
#pragma unroll
        for (int j = 0; j < 8; j++) {
            const int n = n0 + tn + j;       // 0..1023
            const int h = n >> 6;            // /64
            const int d = n & 63;
            out[(((size_t)bb * NH_ + h) * S_ + ss) * HD_ + d] = acc[i][j] + bias[n];
        }
    }
}

// ---------------------------------------------------------------------------
// Kernel 2: fp32 flash attention, causal.
// One CTA = 128 query rows of one (b,h). One thread = one query row.
// Q row (64), O accumulator (64), score tile (32) in registers.
// K/V tiles 32x64 in smem (broadcast reads).
// ---------------------------------------------------------------------------
__global__ __launch_bounds__(128)
void flash_attn(const float* __restrict__ mask, float* __restrict__ out)
{
    __shared__ float Ks[32 * 64];
    __shared__ float Vs[32 * 64];
    __shared__ float Ms[32];

    const int qt  = blockIdx.x;          // 0..15
    const int h   = blockIdx.y;          // 0..15
    const int b   = blockIdx.z;          // 0..3
    const int tid = threadIdx.x;
    const int qi  = qt * 128 + tid;      // query index, always < S_

    const size_t headbase = ((size_t)b * NH_ + h) * S_ * HD_;
    const float* __restrict__ qptr  = &g_q[headbase + (size_t)qi * HD_];
    const float* __restrict__ kbase = &g_k[headbase];
    const float* __restrict__ vbase = &g_v[headbase];

    float q[64];
#pragma unroll
    for (int i = 0; i < 16; i++) {
        float4 v = *(const float4*)&qptr[i * 4];
        q[i * 4 + 0] = v.x; q[i * 4 + 1] = v.y;
        q[i * 4 + 2] = v.z; q[i * 4 + 3] = v.w;
    }

    float o[64];
#pragma unroll
    for (int d = 0; d < 64; d++) o[d] = 0.f;
    float mrun = -INFINITY, l = 0.f;

    const int nk = qt * 4 + 4;           // key tiles of 32 covering causal span
    const float scale = 0.125f;          // 1/sqrt(64)

    for (int kt = 0; kt < nk; kt++) {
        // cooperative K/V tile load (2048 floats each, fully coalesced)
        const float* kg = kbase + (size_t)kt * 32 * 64;
        const float* vg = vbase + (size_t)kt * 32 * 64;
#pragma unroll
        for (int i = 0; i < 4; i++) {
            const int idx = (i * 128 + tid) * 4;
            *(float4*)&Ks[idx] = *(const float4*)&kg[idx];
            *(float4*)&Vs[idx] = *(const float4*)&vg[idx];
        }
        if (tid < 32) Ms[tid] = mask[(size_t)b * S_ + kt * 32 + tid];
        __syncthreads();

        if (kt * 32 <= qi) {             // skip fully-masked tiles for this row
            float p[32];
            float mt = -INFINITY;
#pragma unroll
            for (int j = 0; j < 32; j++) {
                const int kj = kt * 32 + j;
                float s = 0.f;
                const float4* kr = (const float4*)&Ks[j * 64];
#pragma unroll
                for (int d4 = 0; d4 < 16; d4++) {
                    float4 kv = kr[d4];
                    s += q[d4 * 4 + 0] * kv.x;
                    s += q[d4 * 4 + 1] * kv.y;
                    s += q[d4 * 4 + 2] * kv.z;
                    s += q[d4 * 4 + 3] * kv.w;
                }
                s = (s + Ms[j]) * scale;
                if (kj > qi) s = -INFINITY;
                p[j] = s;
                mt = fmaxf(mt, s);
            }
            const float mnew = fmaxf(mrun, mt);
            const float corr = __expf(mrun - mnew);   // 0 on first tile
            l *= corr;
#pragma unroll
            for (int d = 0; d < 64; d++) o[d] *= corr;

#pragma unroll
            for (int j = 0; j < 32; j++) {
                const float pj = __expf(p[j] - mnew); // 0 for masked
                l += pj;
                const float4* vr = (const float4*)&Vs[j * 64];
#pragma unroll
                for (int d4 = 0; d4 < 16; d4++) {
                    float4 vv = vr[d4];
                    o[d4 * 4 + 0] += pj * vv.x;
                    o[d4 * 4 + 1] += pj * vv.y;
                    o[d4 * 4 + 2] += pj * vv.z;
                    o[d4 * 4 + 3] += pj * vv.w;
                }
            }
            mrun = mnew;
        }
        __syncthreads();
    }

    const float inv = 1.f / l;
    float* op = &out[((size_t)b * S_ + qi) * H_ + h * HD_];
#pragma unroll
    for (int i = 0; i < 16; i++) {
        float4 v;
        v.x = o[i * 4 + 0] * inv; v.y = o[i * 4 + 1] * inv;
        v.z = o[i * 4 + 2] * inv; v.w = o[i * 4 + 3] * inv;
        *(float4*)&op[i * 4] = v;
    }
}

// ---------------------------------------------------------------------------
extern "C" void kernel_launch(void* const* d_in, const int* in_sizes, int n_in,
                              void* d_out, int out_size)
{
    const float* hs   = (const float*)d_in[0];
    const float* mask = (const float*)d_in[1];
    const float* Wq   = (const float*)d_in[2];
    const float* bq   = (const float*)d_in[3];
    const float* Wk   = (const float*)d_in[4];
    const float* bk   = (const float*)d_in[5];
    const float* Wv   = (const float*)d_in[6];
    const float* bv   = (const float*)d_in[7];
    float* out = (float*)d_out;

    qkv_proj<<<dim3(64, 24), 256>>>(hs, Wq, bq, Wk, bk, Wv, bv);
    flash_attn<<<dim3(16, NH_, B_), 128>>>(mask, out);
}

// round 3
// speedup vs baseline: 1.2721x; 1.2721x over previous
#include <cuda_runtime.h>
#include <math.h>
#include <stdint.h>

#define B_  4
#define S_  2048
#define H_  1024
#define NH_ 16
#define HD_ 64
#define QKV_ELEMS (B_*NH_*S_*HD_)

// Scratch (no cudaMalloc allowed): Q/K/V in split-head layout [B, NH, S, HD]
__device__ float g_q[QKV_ELEMS];
__device__ float g_k[QKV_ELEMS];
__device__ float g_v[QKV_ELEMS];

__device__ __forceinline__ uint32_t f2tf32(float x) {
    uint32_t r;
    asm("cvt.rn.tf32.f32 %0, %1;" : "=r"(r) : "f"(x));
    return r;
}

__device__ __forceinline__ void mma_tf32(float& c0, float& c1, float& c2, float& c3,
                                         uint32_t a0, uint32_t a1, uint32_t a2, uint32_t a3,
                                         uint32_t b0, uint32_t b1) {
    asm volatile(
        "mma.sync.aligned.m16n8k8.row.col.f32.tf32.tf32.f32 "
        "{%0,%1,%2,%3}, {%4,%5,%6,%7}, {%8,%9}, {%0,%1,%2,%3};"
        : "+f"(c0), "+f"(c1), "+f"(c2), "+f"(c3)
        : "r"(a0), "r"(a1), "r"(a2), "r"(a3), "r"(b0), "r"(b1));
}

// ---------------------------------------------------------------------------
// Kernel 1: QKV projection via mma.sync tf32 (HMMA path; tcgen05 unavailable
// at compute_103). C[m,n] = sum_k X[m,k] * W[n,k] + bias[n].
// CTA tile 128x128, 8 warps (2x4), warp tile 64x32, K-chunk 32.
// Smem rows padded to 36 words -> conflict-free STS and fragment LDS.
// ---------------------------------------------------------------------------
#define LDA 36
__global__ __launch_bounds__(256)
void qkv_mma(const float* __restrict__ X,
             const float* __restrict__ Wq, const float* __restrict__ bq,
             const float* __restrict__ Wk, const float* __restrict__ bk,
             const float* __restrict__ Wv, const float* __restrict__ bv)
{
    __shared__ uint32_t As[128 * LDA];   // [m][k] tf32 bits
    __shared__ uint32_t Bs[128 * LDA];   // [n][k] tf32 bits

    const int tid  = threadIdx.x;
    const int wid  = tid >> 5;
    const int lane = tid & 31;
    const int wm0  = (wid >> 2) * 64;    // warp m-offset (0,64)
    const int wn0  = (wid & 3) * 32;     // warp n-offset (0,32,64,96)

    const int m0 = blockIdx.x * 128;
    const int nb = blockIdx.y;
    const int sel = nb >> 3;
    const int n0  = (nb & 7) * 128;

    const float* __restrict__ W    = (sel == 0) ? Wq : (sel == 1) ? Wk : Wv;
    const float* __restrict__ bias = (sel == 0) ? bq : (sel == 1) ? bk : bv;
    float* __restrict__ outp       = (sel == 0) ? g_q : (sel == 1) ? g_k : g_v;

    float acc[4][4][4];
#pragma unroll
    for (int i = 0; i < 4; i++)
#pragma unroll
        for (int j = 0; j < 4; j++)
#pragma unroll
            for (int r = 0; r < 4; r++) acc[i][j][r] = 0.f;

    // per-thread global load coords: 4 float4 each for A and B per chunk
    const int lrow0 = tid >> 3;          // 0..31, +32 per iter
    const int lc4   = tid & 7;           // float4 column 0..7

    const int qrow = lane >> 2;          // fragment row-in-8
    const int qcol = lane & 3;           // fragment k-in-4

    for (int k0 = 0; k0 < 1024; k0 += 32) {
#pragma unroll
        for (int i = 0; i < 4; i++) {
            const int row = i * 32 + lrow0;
            float4 av  = *(const float4*)&X[(size_t)(m0 + row) * 1024 + k0 + lc4 * 4];
            float4 bv4 = *(const float4*)&W[(size_t)(n0 + row) * 1024 + k0 + lc4 * 4];
            uint4 at, bt;
            at.x = f2tf32(av.x);  at.y = f2tf32(av.y);
            at.z = f2tf32(av.z);  at.w = f2tf32(av.w);
            bt.x = f2tf32(bv4.x); bt.y = f2tf32(bv4.y);
            bt.z = f2tf32(bv4.z); bt.w = f2tf32(bv4.w);
            *(uint4*)&As[row * LDA + lc4 * 4] = at;
            *(uint4*)&Bs[row * LDA + lc4 * 4] = bt;
        }
        __syncthreads();

#pragma unroll
        for (int ks = 0; ks < 32; ks += 8) {
            uint32_t af[4][4], bf[4][2];
#pragma unroll
            for (int i = 0; i < 4; i++) {
                const uint32_t* ap = &As[(wm0 + i * 16 + qrow) * LDA + ks + qcol];
                af[i][0] = ap[0];
                af[i][1] = ap[8 * LDA];
                af[i][2] = ap[4];
                af[i][3] = ap[8 * LDA + 4];
            }
#pragma unroll
            for (int j = 0; j < 4; j++) {
                const uint32_t* bp = &Bs[(wn0 + j * 8 + qrow) * LDA + ks + qcol];
                bf[j][0] = bp[0];
                bf[j][1] = bp[4];
            }
#pragma unroll
            for (int i = 0; i < 4; i++)
#pragma unroll
                for (int j = 0; j < 4; j++)
                    mma_tf32(acc[i][j][0], acc[i][j][1], acc[i][j][2], acc[i][j][3],
                             af[i][0], af[i][1], af[i][2], af[i][3],
                             bf[j][0], bf[j][1]);
        }
        __syncthreads();
    }

    // Epilogue: bias add + scatter into split-head [B,NH,S,HD]
#pragma unroll
    for (int j = 0; j < 4; j++) {
        const int n = n0 + wn0 + j * 8 + (lane & 3) * 2;   // even, pair stays in-head
        const int h = n >> 6;
        const int d = n & 63;
        const float b0v = bias[n];
        const float b1v = bias[n + 1];
#pragma unroll
        for (int i = 0; i < 4; i++) {
            const int mA = m0 + wm0 + i * 16 + (lane >> 2);
            const int mB = mA + 8;
            {
                const int bb = mA >> 11, ss = mA & 2047;
                float2 v; v.x = acc[i][j][0] + b0v; v.y = acc[i][j][1] + b1v;
                *(float2*)&outp[(((size_t)bb * NH_ + h) * S_ + ss) * HD_ + d] = v;
            }
            {
                const int bb = mB >> 11, ss = mB & 2047;
                float2 v; v.x = acc[i][j][2] + b0v; v.y = acc[i][j][3] + b1v;
                *(float2*)&outp[(((size_t)bb * NH_ + h) * S_ + ss) * HD_ + d] = v;
            }
        }
    }
}

// ---------------------------------------------------------------------------
// Kernel 2: fp32 flash attention, causal. 256 threads = 128 query rows x 2
// d-halves. Online softmax over 8-key sub-tiles (p[8] in regs), shfl-xor(1)
// combines the two half-dot-products. Targets 2 CTAs/SM (16 warps).
// ---------------------------------------------------------------------------
__global__ __launch_bounds__(256, 2)
void flash_attn(const float* __restrict__ mask, float* __restrict__ out)
{
    __shared__ float Ks[32 * 64];
    __shared__ float Vs[32 * 64];
    __shared__ float Ms[32];

    const int qt  = blockIdx.x;
    const int h   = blockIdx.y;
    const int b   = blockIdx.z;
    const int tid = threadIdx.x;
    const int row  = tid >> 1;
    const int half = tid & 1;
    const int qi   = qt * 128 + row;

    const size_t headbase = ((size_t)b * NH_ + h) * S_ * HD_;
    const float* __restrict__ qptr  = &g_q[headbase + (size_t)qi * HD_ + half * 32];
    const float* __restrict__ kbase = &g_k[headbase];
    const float* __restrict__ vbase = &g_v[headbase];

    float q[32];
#pragma unroll
    for (int i = 0; i < 8; i++) {
        float4 v = *(const float4*)&qptr[i * 4];
        q[i * 4 + 0] = v.x; q[i * 4 + 1] = v.y;
        q[i * 4 + 2] = v.z; q[i * 4 + 3] = v.w;
    }
    float o[32];
#pragma unroll
    for (int d = 0; d < 32; d++) o[d] = 0.f;
    float mrun = -INFINITY, l = 0.f;

    const int nk = qt * 4 + 4;
    const float scale = 0.125f;

    for (int kt = 0; kt < nk; kt++) {
        const float* kg = kbase + (size_t)kt * 32 * 64;
        const float* vg = vbase + (size_t)kt * 32 * 64;
#pragma unroll
        for (int i = 0; i < 2; i++) {
            const int idx = (i * 256 + tid) * 4;
            *(float4*)&Ks[idx] = *(const float4*)&kg[idx];
            *(float4*)&Vs[idx] = *(const float4*)&vg[idx];
        }
        if (tid < 32) Ms[tid] = mask[(size_t)b * S_ + kt * 32 + tid];
        __syncthreads();

        if (kt * 32 <= qi) {
#pragma unroll
            for (int st = 0; st < 4; st++) {       // 8-key sub-tiles
                float p[8];
                float mt = -INFINITY;
#pragma unroll
                for (int jj = 0; jj < 8; jj++) {
                    const int j = st * 8 + jj;
                    const int kj = kt * 32 + j;
                    const float4* kr = (const float4*)&Ks[j * 64 + half * 32];
                    float s = 0.f;
#pragma unroll
                    for (int d4 = 0; d4 < 8; d4++) {
                        float4 kv = kr[d4];
                        s += q[d4 * 4 + 0] * kv.x;
                        s += q[d4 * 4 + 1] * kv.y;
                        s += q[d4 * 4 + 2] * kv.z;
                        s += q[d4 * 4 + 3] * kv.w;
                    }
                    s += __shfl_xor_sync(0xffffffffu, s, 1);
                    s = (s + Ms[j]) * scale;
                    if (kj > qi) s = -INFINITY;
                    p[jj] = s;
                    mt = fmaxf(mt, s);
                }
                if (mt > mrun) {
                    const float corr = __expf(mrun - mt);  // 0 on first sub-tile
                    l *= corr;
#pragma unroll
                    for (int d = 0; d < 32; d++) o[d] *= corr;
                    mrun = mt;
                }
#pragma unroll
                for (int jj = 0; jj < 8; jj++) {
                    const float pj = __expf(p[jj] - mrun);
                    l += pj;
                    const float4* vr = (const float4*)&Vs[(st * 8 + jj) * 64 + half * 32];
#pragma unroll
                    for (int d4 = 0; d4 < 8; d4++) {
                        float4 vv = vr[d4];
                        o[d4 * 4 + 0] += pj * vv.x;
                        o[d4 * 4 + 1] += pj * vv.y;
                        o[d4 * 4 + 2] += pj * vv.z;
                        o[d4 * 4 + 3] += pj * vv.w;
                    }
                }
            }
        }
        __syncthreads();
    }

    const float inv = 1.f / l;
    float* op = &out[((size_t)b * S_ + qi) * H_ + h * HD_ + half * 32];
#pragma unroll
    for (int i = 0; i < 8; i++) {
        float4 v;
        v.x = o[i * 4 + 0] * inv; v.y = o[i * 4 + 1] * inv;
        v.z = o[i * 4 + 2] * inv; v.w = o[i * 4 + 3] * inv;
        *(float4*)&op[i * 4] = v;
    }
}

// ---------------------------------------------------------------------------
extern "C" void kernel_launch(void* const* d_in, const int* in_sizes, int n_in,
                              void* d_out, int out_size)
{
    const float* hs   = (const float*)d_in[0];
    const float* mask = (const float*)d_in[1];
    const float* Wq   = (const float*)d_in[2];
    const float* bq   = (const float*)d_in[3];
    const float* Wk   = (const float*)d_in[4];
    const float* bk   = (const float*)d_in[5];
    const float* Wv   = (const float*)d_in[6];
    const float* bv   = (const float*)d_in[7];
    float* out = (float*)d_out;

    qkv_mma<<<dim3(64, 24), 256>>>(hs, Wq, bq, Wk, bk, Wv, bv);
    flash_attn<<<dim3(16, NH_, B_), 256>>>(mask, out);
}

// round 4
// speedup vs baseline: 6.6516x; 5.2290x over previous
#include <cuda_runtime.h>
#include <cuda_fp16.h>
#include <math.h>
#include <stdint.h>

#define B_  4
#define S_  2048
#define H_  1024
#define NH_ 16
#define HD_ 64
#define QKV_ELEMS (B_*NH_*S_*HD_)

// Scratch (no cudaMalloc): Q,K fp16 [B,NH,S,HD]; V fp16 TRANSPOSED [B,NH,HD,S]
__device__ __half g_q[QKV_ELEMS];
__device__ __half g_k[QKV_ELEMS];
__device__ __half g_vt[QKV_ELEMS];

__device__ __forceinline__ uint32_t f2tf32(float x) {
    uint32_t r;
    asm("cvt.rn.tf32.f32 %0, %1;" : "=r"(r) : "f"(x));
    return r;
}
__device__ __forceinline__ uint32_t packh2(float lo, float hi) {
    uint32_t r;
    asm("cvt.rn.f16x2.f32 %0, %1, %2;" : "=r"(r) : "f"(hi), "f"(lo));
    return r;
}
__device__ __forceinline__ void mma_tf32(float& c0, float& c1, float& c2, float& c3,
                                         uint32_t a0, uint32_t a1, uint32_t a2, uint32_t a3,
                                         uint32_t b0, uint32_t b1) {
    asm volatile(
        "mma.sync.aligned.m16n8k8.row.col.f32.tf32.tf32.f32 "
        "{%0,%1,%2,%3}, {%4,%5,%6,%7}, {%8,%9}, {%0,%1,%2,%3};"
        : "+f"(c0), "+f"(c1), "+f"(c2), "+f"(c3)
        : "r"(a0), "r"(a1), "r"(a2), "r"(a3), "r"(b0), "r"(b1));
}
__device__ __forceinline__ void mma_f16(float* c,
                                        const uint32_t* a, uint32_t b0, uint32_t b1) {
    asm volatile(
        "mma.sync.aligned.m16n8k16.row.col.f32.f16.f16.f32 "
        "{%0,%1,%2,%3}, {%4,%5,%6,%7}, {%8,%9}, {%0,%1,%2,%3};"
        : "+f"(c[0]), "+f"(c[1]), "+f"(c[2]), "+f"(c[3])
        : "r"(a[0]), "r"(a[1]), "r"(a[2]), "r"(a[3]), "r"(b0), "r"(b1));
}

// ---------------------------------------------------------------------------
// Kernel 1: QKV projection (tf32 mma.sync), fp16 outputs.
// C[m,n] = sum_k X[m,k]*W[n,k] + bias[n].  CTA 128x128, 8 warps, warp 64x32.
// Q,K written [b,h][s][d] fp16; V written TRANSPOSED [b,h][d][s] fp16.
// ---------------------------------------------------------------------------
#define LDA 36
__global__ __launch_bounds__(256)
void qkv_mma(const float* __restrict__ X,
             const float* __restrict__ Wq, const float* __restrict__ bq,
             const float* __restrict__ Wk, const float* __restrict__ bk,
             const float* __restrict__ Wv, const float* __restrict__ bv)
{
    __shared__ uint32_t As[128 * LDA];
    __shared__ uint32_t Bs[128 * LDA];

    const int tid  = threadIdx.x;
    const int wid  = tid >> 5;
    const int lane = tid & 31;
    const int wm0  = (wid >> 2) * 64;
    const int wn0  = (wid & 3) * 32;

    const int m0 = blockIdx.x * 128;
    const int nb = blockIdx.y;
    const int sel = nb >> 3;
    const int n0  = (nb & 7) * 128;

    const float* __restrict__ W    = (sel == 0) ? Wq : (sel == 1) ? Wk : Wv;
    const float* __restrict__ bias = (sel == 0) ? bq : (sel == 1) ? bk : bv;

    float acc[4][4][4];
#pragma unroll
    for (int i = 0; i < 4; i++)
#pragma unroll
        for (int j = 0; j < 4; j++)
#pragma unroll
            for (int r = 0; r < 4; r++) acc[i][j][r] = 0.f;

    const int lrow0 = tid >> 3;
    const int lc4   = tid & 7;
    const int qrow = lane >> 2;
    const int qcol = lane & 3;

    for (int k0 = 0; k0 < 1024; k0 += 32) {
#pragma unroll
        for (int i = 0; i < 4; i++) {
            const int row = i * 32 + lrow0;
            float4 av  = *(const float4*)&X[(size_t)(m0 + row) * 1024 + k0 + lc4 * 4];
            float4 bv4 = *(const float4*)&W[(size_t)(n0 + row) * 1024 + k0 + lc4 * 4];
            uint4 at, bt;
            at.x = f2tf32(av.x);  at.y = f2tf32(av.y);
            at.z = f2tf32(av.z);  at.w = f2tf32(av.w);
            bt.x = f2tf32(bv4.x); bt.y = f2tf32(bv4.y);
            bt.z = f2tf32(bv4.z); bt.w = f2tf32(bv4.w);
            *(uint4*)&As[row * LDA + lc4 * 4] = at;
            *(uint4*)&Bs[row * LDA + lc4 * 4] = bt;
        }
        __syncthreads();
#pragma unroll
        for (int ks = 0; ks < 32; ks += 8) {
            uint32_t af[4][4], bf[4][2];
#pragma unroll
            for (int i = 0; i < 4; i++) {
                const uint32_t* ap = &As[(wm0 + i * 16 + qrow) * LDA + ks + qcol];
                af[i][0] = ap[0];
                af[i][1] = ap[8 * LDA];
                af[i][2] = ap[4];
                af[i][3] = ap[8 * LDA + 4];
            }
#pragma unroll
            for (int j = 0; j < 4; j++) {
                const uint32_t* bp = &Bs[(wn0 + j * 8 + qrow) * LDA + ks + qcol];
                bf[j][0] = bp[0];
                bf[j][1] = bp[4];
            }
#pragma unroll
            for (int i = 0; i < 4; i++)
#pragma unroll
                for (int j = 0; j < 4; j++)
                    mma_tf32(acc[i][j][0], acc[i][j][1], acc[i][j][2], acc[i][j][3],
                             af[i][0], af[i][1], af[i][2], af[i][3],
                             bf[j][0], bf[j][1]);
        }
        __syncthreads();
    }

    // Epilogue: bias + fp16 store. Q/K: [b,h][s][d]; V: transposed [b,h][d][s].
#pragma unroll
    for (int j = 0; j < 4; j++) {
        const int n = n0 + wn0 + j * 8 + (lane & 3) * 2;
        const int h = n >> 6;
        const int d = n & 63;
        const float b0v = bias[n];
        const float b1v = bias[n + 1];
#pragma unroll
        for (int i = 0; i < 4; i++) {
            const int mA = m0 + wm0 + i * 16 + (lane >> 2);
            const int mB = mA + 8;
            const int bbA = mA >> 11, ssA = mA & 2047;
            const int bbB = mB >> 11, ssB = mB & 2047;
            if (sel == 2) {
                __half* vt = g_vt;
                const size_t base = ((size_t)bbA * NH_ + h) * HD_;
                vt[(base + d)     * S_ + ssA] = __float2half(acc[i][j][0] + b0v);
                vt[(base + d + 1) * S_ + ssA] = __float2half(acc[i][j][1] + b1v);
                const size_t baseB = ((size_t)bbB * NH_ + h) * HD_;
                vt[(baseB + d)     * S_ + ssB] = __float2half(acc[i][j][2] + b0v);
                vt[(baseB + d + 1) * S_ + ssB] = __float2half(acc[i][j][3] + b1v);
            } else {
                __half* dst = (sel == 0) ? g_q : g_k;
                *(__half2*)&dst[(((size_t)bbA * NH_ + h) * S_ + ssA) * HD_ + d] =
                    __floats2half2_rn(acc[i][j][0] + b0v, acc[i][j][1] + b1v);
                *(__half2*)&dst[(((size_t)bbB * NH_ + h) * S_ + ssB) * HD_ + d] =
                    __floats2half2_rn(acc[i][j][2] + b0v, acc[i][j][3] + b1v);
            }
        }
    }
}

// ---------------------------------------------------------------------------
// Kernel 2: flash attention on mma.sync fp16 (fp32 accum).
// CTA = 128 q-rows of one (b,h); 4 warps, warp = 32 rows (two m16 sub-tiles
// sharing B-fragments). Key tiles of 64. S C-frags pack directly into P
// A-frags (fp16 layout identity). V pre-transposed in gmem.
// ---------------------------------------------------------------------------
#define LDH 72   // padded half-stride for smem tiles
__global__ __launch_bounds__(128, 2)
void flash_mma(const float* __restrict__ mask, float* __restrict__ out)
{
    __shared__ __half Qs[128 * LDH];
    __shared__ __half Ks[64 * LDH];
    __shared__ __half Vts[64 * LDH];
    __shared__ float Ms[64];

    const int qt = 15 - blockIdx.x;       // heavy tiles first
    const int h  = blockIdx.y;
    const int b  = blockIdx.z;
    const int tid  = threadIdx.x;
    const int w    = tid >> 5;
    const int lane = tid & 31;
    const int r = lane >> 2;
    const int c = lane & 3;

    const int q0 = qt * 128;
    const size_t hb = ((size_t)b * NH_ + h) * S_;

    // Load Q tile (128 x 64 fp16)
    {
        const __half* qg = g_q + (hb + q0) * HD_;
#pragma unroll
        for (int i = 0; i < 8; i++) {
            const int idx = i * 128 + tid;
            const int row = idx >> 3, c8 = idx & 7;
            *(uint4*)&Qs[row * LDH + c8 * 8] = *(const uint4*)&qg[row * HD_ + c8 * 8];
        }
    }
    __syncthreads();

    // Q fragments: [mi][kc][4], rows w*32+mi*16+{r,r+8}, d = kc*16+{2c,2c+1,+8}
    uint32_t qfr[2][4][4];
#pragma unroll
    for (int mi = 0; mi < 2; mi++)
#pragma unroll
        for (int kc = 0; kc < 4; kc++) {
            const __half* p = &Qs[(w * 32 + mi * 16 + r) * LDH + kc * 16 + 2 * c];
            qfr[mi][kc][0] = *(const uint32_t*)p;
            qfr[mi][kc][1] = *(const uint32_t*)(p + 8 * LDH);
            qfr[mi][kc][2] = *(const uint32_t*)(p + 8);
            qfr[mi][kc][3] = *(const uint32_t*)(p + 8 * LDH + 8);
        }

    float of[2][8][4];
#pragma unroll
    for (int mi = 0; mi < 2; mi++)
#pragma unroll
        for (int nf = 0; nf < 8; nf++)
#pragma unroll
            for (int e = 0; e < 4; e++) of[mi][nf][e] = 0.f;
    float mrun[2][2] = {{-INFINITY, -INFINITY}, {-INFINITY, -INFINITY}};
    float lsum[2][2] = {{0.f, 0.f}, {0.f, 0.f}};

    const int qr_lo = q0 + w * 32;
    const int nkt = 2 * qt + 2;

    for (int kt = 0; kt < nkt; kt++) {
        __syncthreads();
        // cooperative K / Vt / mask tile loads
        {
            const __half* kg = g_k + (hb + kt * 64) * HD_;
            const __half* vg = g_vt + ((size_t)b * NH_ + h) * HD_ * S_ + kt * 64;
#pragma unroll
            for (int i = 0; i < 4; i++) {
                const int idx = i * 128 + tid;
                const int row = idx >> 3, c8 = idx & 7;
                *(uint4*)&Ks[row * LDH + c8 * 8]  = *(const uint4*)&kg[row * HD_ + c8 * 8];
                *(uint4*)&Vts[row * LDH + c8 * 8] = *(const uint4*)&vg[(size_t)row * S_ + c8 * 8];
            }
            if (tid < 64) Ms[tid] = mask[(size_t)b * S_ + kt * 64 + tid];
        }
        __syncthreads();

        if (kt * 64 > qr_lo + 31) continue;   // fully masked for this warp

        // ---- S = Q K^T (fp32 accum) ----
        float sf[2][8][4];
#pragma unroll
        for (int mi = 0; mi < 2; mi++)
#pragma unroll
            for (int nf = 0; nf < 8; nf++)
#pragma unroll
                for (int e = 0; e < 4; e++) sf[mi][nf][e] = 0.f;
#pragma unroll
        for (int kc = 0; kc < 4; kc++)
#pragma unroll
            for (int nf = 0; nf < 8; nf++) {
                const __half* p = &Ks[(nf * 8 + r) * LDH + kc * 16 + 2 * c];
                const uint32_t b0 = *(const uint32_t*)p;
                const uint32_t b1 = *(const uint32_t*)(p + 8);
                mma_f16(sf[0][nf], qfr[0][kc], b0, b1);
                mma_f16(sf[1][nf], qfr[1][kc], b0, b1);
            }

        // ---- scale + mask + online softmax + rescale O ----
        const bool diag = (kt * 64 + 63) > qr_lo;   // any masking for this warp
        uint32_t pf[2][4][4];
#pragma unroll
        for (int mi = 0; mi < 2; mi++) {
            const int rowA = qr_lo + mi * 16 + r;
#pragma unroll
            for (int nf = 0; nf < 8; nf++) {
                const int col0 = kt * 64 + nf * 8 + 2 * c;
                const float m0v = Ms[nf * 8 + 2 * c];
                const float m1v = Ms[nf * 8 + 2 * c + 1];
                sf[mi][nf][0] = (sf[mi][nf][0] + m0v) * 0.125f;
                sf[mi][nf][1] = (sf[mi][nf][1] + m1v) * 0.125f;
                sf[mi][nf][2] = (sf[mi][nf][2] + m0v) * 0.125f;
                sf[mi][nf][3] = (sf[mi][nf][3] + m1v) * 0.125f;
                if (diag) {
                    if (col0     > rowA)     sf[mi][nf][0] = -INFINITY;
                    if (col0 + 1 > rowA)     sf[mi][nf][1] = -INFINITY;
                    if (col0     > rowA + 8) sf[mi][nf][2] = -INFINITY;
                    if (col0 + 1 > rowA + 8) sf[mi][nf][3] = -INFINITY;
                }
            }
#pragma unroll
            for (int rr = 0; rr < 2; rr++) {
                float mt = -INFINITY;
#pragma unroll
                for (int nf = 0; nf < 8; nf++)
                    mt = fmaxf(mt, fmaxf(sf[mi][nf][rr * 2], sf[mi][nf][rr * 2 + 1]));
                mt = fmaxf(mt, __shfl_xor_sync(0xffffffffu, mt, 1));
                mt = fmaxf(mt, __shfl_xor_sync(0xffffffffu, mt, 2));
                const float mn = fmaxf(mrun[mi][rr], mt);
                const float corr = __expf(mrun[mi][rr] - mn);
                mrun[mi][rr] = mn;
                float ls = 0.f;
#pragma unroll
                for (int nf = 0; nf < 8; nf++) {
                    const float p0 = __expf(sf[mi][nf][rr * 2]     - mn);
                    const float p1 = __expf(sf[mi][nf][rr * 2 + 1] - mn);
                    sf[mi][nf][rr * 2] = p0;
                    sf[mi][nf][rr * 2 + 1] = p1;
                    ls += p0 + p1;
                }
                ls += __shfl_xor_sync(0xffffffffu, ls, 1);
                ls += __shfl_xor_sync(0xffffffffu, ls, 2);
                lsum[mi][rr] = lsum[mi][rr] * corr + ls;
#pragma unroll
                for (int nf = 0; nf < 8; nf++) {
                    of[mi][nf][rr * 2]     *= corr;
                    of[mi][nf][rr * 2 + 1] *= corr;
                }
            }
            // pack P into fp16 A-fragments (C-layout == A-layout identity)
#pragma unroll
            for (int kc = 0; kc < 4; kc++) {
                pf[mi][kc][0] = packh2(sf[mi][2 * kc][0],     sf[mi][2 * kc][1]);
                pf[mi][kc][1] = packh2(sf[mi][2 * kc][2],     sf[mi][2 * kc][3]);
                pf[mi][kc][2] = packh2(sf[mi][2 * kc + 1][0], sf[mi][2 * kc + 1][1]);
                pf[mi][kc][3] = packh2(sf[mi][2 * kc + 1][2], sf[mi][2 * kc + 1][3]);
            }
        }

        // ---- O += P V ----
#pragma unroll
        for (int kc = 0; kc < 4; kc++)
#pragma unroll
            for (int nd = 0; nd < 8; nd++) {
                const __half* p = &Vts[(nd * 8 + r) * LDH + kc * 16 + 2 * c];
                const uint32_t b0 = *(const uint32_t*)p;
                const uint32_t b1 = *(const uint32_t*)(p + 8);
                mma_f16(of[0][nd], pf[0][kc], b0, b1);
                mma_f16(of[1][nd], pf[1][kc], b0, b1);
            }
    }

    // ---- normalize + store ----
#pragma unroll
    for (int mi = 0; mi < 2; mi++)
#pragma unroll
        for (int rr = 0; rr < 2; rr++) {
            const float inv = 1.f / lsum[mi][rr];
            const int row = q0 + w * 32 + mi * 16 + r + rr * 8;
            float* op = out + ((size_t)b * S_ + row) * H_ + h * HD_;
#pragma unroll
            for (int nf = 0; nf < 8; nf++) {
                float2 v;
                v.x = of[mi][nf][rr * 2] * inv;
                v.y = of[mi][nf][rr * 2 + 1] * inv;
                *(float2*)&op[nf * 8 + 2 * c] = v;
            }
        }
}

// ---------------------------------------------------------------------------
extern "C" void kernel_launch(void* const* d_in, const int* in_sizes, int n_in,
                              void* d_out, int out_size)
{
    const float* hs   = (const float*)d_in[0];
    const float* mask = (const float*)d_in[1];
    const float* Wq   = (const float*)d_in[2];
    const float* bq   = (const float*)d_in[3];
    const float* Wk   = (const float*)d_in[4];
    const float* bk   = (const float*)d_in[5];
    const float* Wv   = (const float*)d_in[6];
    const float* bv   = (const float*)d_in[7];
    float* out = (float*)d_out;

    qkv_mma<<<dim3(64, 24), 256>>>(hs, Wq, bq, Wk, bk, Wv, bv);
    flash_mma<<<dim3(16, NH_, B_), 128>>>(mask, out);
}

// round 5
// speedup vs baseline: 9.5510x; 1.4359x over previous
#include <cuda_runtime.h>
#include <cuda_fp16.h>
#include <math.h>
#include <stdint.h>

#define B_  4
#define S_  2048
#define H_  1024
#define NH_ 16
#define HD_ 64
#define QKV_ELEMS (B_*NH_*S_*HD_)
#define XH_ELEMS  (B_*S_*H_)       // 8,388,608
#define WH_ELEMS  (H_*H_)          // 1,048,576

// Scratch (no cudaMalloc): Q,K fp16 [B,NH,S,HD]; V fp16 TRANSPOSED [B,NH,HD,S]
__device__ __half g_q[QKV_ELEMS];
__device__ __half g_k[QKV_ELEMS];
__device__ __half g_vt[QKV_ELEMS];
// fp16 copies of activations / weights for cp.async GEMM
__device__ __half g_xh[XH_ELEMS];
__device__ __half g_wh[3 * WH_ELEMS];

__device__ __forceinline__ uint32_t packh2(float lo, float hi) {
    uint32_t r;
    asm("cvt.rn.f16x2.f32 %0, %1, %2;" : "=r"(r) : "f"(hi), "f"(lo));
    return r;
}
__device__ __forceinline__ void mma_f16(float* c,
                                        const uint32_t* a, uint32_t b0, uint32_t b1) {
    asm volatile(
        "mma.sync.aligned.m16n8k16.row.col.f32.f16.f16.f32 "
        "{%0,%1,%2,%3}, {%4,%5,%6,%7}, {%8,%9}, {%0,%1,%2,%3};"
        : "+f"(c[0]), "+f"(c[1]), "+f"(c[2]), "+f"(c[3])
        : "r"(a[0]), "r"(a[1]), "r"(a[2]), "r"(a[3]), "r"(b0), "r"(b1));
}
__device__ __forceinline__ uint32_t smem_u32(const void* p) {
    uint32_t a;
    asm("{ .reg .u64 t; cvta.to.shared.u64 t, %1; cvt.u32.u64 %0, t; }"
        : "=r"(a) : "l"(p));
    return a;
}
__device__ __forceinline__ void cp16(uint32_t s, const void* g) {
    asm volatile("cp.async.cg.shared.global [%0], [%1], 16;"
                 :: "r"(s), "l"(g) : "memory");
}
#define CP_COMMIT() asm volatile("cp.async.commit_group;" ::: "memory")
#define CP_WAIT(n)  asm volatile("cp.async.wait_group %0;" :: "n"(n) : "memory")

// ---------------------------------------------------------------------------
// Kernel 0: fp32 -> fp16 conversion of X and the three weight matrices.
// ---------------------------------------------------------------------------
__global__ __launch_bounds__(256)
void to_half(const float* __restrict__ X,  const float* __restrict__ Wq,
             const float* __restrict__ Wk, const float* __restrict__ Wv)
{
    const int i = blockIdx.x * blockDim.x + threadIdx.x;   // float4 index
    const int XF4 = XH_ELEMS / 4, WF4 = WH_ELEMS / 4;
    const float* src;
    __half* dst;
    int off;
    if (i < XF4)                { src = X;  dst = g_xh;              off = i; }
    else if (i < XF4 + WF4)     { src = Wq; dst = g_wh;              off = i - XF4; }
    else if (i < XF4 + 2 * WF4) { src = Wk; dst = g_wh + WH_ELEMS;   off = i - XF4 - WF4; }
    else if (i < XF4 + 3 * WF4) { src = Wv; dst = g_wh + 2*WH_ELEMS; off = i - XF4 - 2*WF4; }
    else return;
    float4 v = ((const float4*)src)[off];
    __half2* d2 = (__half2*)dst + off * 2;
    d2[0] = __floats2half2_rn(v.x, v.y);
    d2[1] = __floats2half2_rn(v.z, v.w);
}

// ---------------------------------------------------------------------------
// Kernel 1: QKV projection, fp16 mma.sync m16n8k16, cp.async double-buffered.
// C[m,n] = sum_k X[m,k]*W[n,k] + bias[n].  CTA 128x128, 8 warps (2x4),
// warp 64x32, K-chunk 64. Smem rows padded to 72 halves (144B, 16B-aligned).
// ---------------------------------------------------------------------------
#define LDH 72
#define ABUF (128 * LDH)              // halves per buffer
__global__ __launch_bounds__(256)
void qkv_h(const float* __restrict__ bq, const float* __restrict__ bk,
           const float* __restrict__ bv)
{
    extern __shared__ __half sm[];    // [A0 | A1 | B0 | B1]
    __half* smA = sm;
    __half* smB = sm + 2 * ABUF;
    const uint32_t sA0 = smem_u32(smA);
    const uint32_t sB0 = smem_u32(smB);

    const int tid  = threadIdx.x;
    const int wid  = tid >> 5;
    const int lane = tid & 31;
    const int wm0  = (wid >> 2) * 64;
    const int wn0  = (wid & 3) * 32;
    const int r = lane >> 2;
    const int c = lane & 3;

    const int m0 = blockIdx.x * 128;
    const int nb = blockIdx.y;
    const int sel = nb >> 3;
    const int n0  = (nb & 7) * 128;

    const __half* __restrict__ Ag = g_xh + (size_t)m0 * 1024;
    const __half* __restrict__ Bg = g_wh + (size_t)sel * WH_ELEMS + (size_t)n0 * 1024;
    const float* __restrict__ bias = (sel == 0) ? bq : (sel == 1) ? bk : bv;

    const int lrow = tid >> 3;        // 0..31 (+32 per i)
    const int lc8  = tid & 7;         // 16B chunk within 128B row

    // prefetch chunk 0 into buffer 0
    {
        const int k0 = 0;
#pragma unroll
        for (int i = 0; i < 4; i++) {
            const int row = i * 32 + lrow;
            const uint32_t so = (uint32_t)(row * LDH + lc8 * 8) * 2;
            cp16(sA0 + so, &Ag[(size_t)row * 1024 + k0 + lc8 * 8]);
            cp16(sB0 + so, &Bg[(size_t)row * 1024 + k0 + lc8 * 8]);
        }
        CP_COMMIT();
    }

    float acc[4][4][4];
#pragma unroll
    for (int mi = 0; mi < 4; mi++)
#pragma unroll
        for (int nj = 0; nj < 4; nj++)
#pragma unroll
            for (int e = 0; e < 4; e++) acc[mi][nj][e] = 0.f;

    for (int ch = 0; ch < 16; ch++) {
        const int buf = ch & 1;
        if (ch + 1 < 16) {            // prefetch next chunk into other buffer
            const int nb2 = (ch + 1) & 1;
            const int k0 = (ch + 1) * 64;
#pragma unroll
            for (int i = 0; i < 4; i++) {
                const int row = i * 32 + lrow;
                const uint32_t so = (uint32_t)(nb2 * ABUF + row * LDH + lc8 * 8) * 2;
                cp16(sA0 + so, &Ag[(size_t)row * 1024 + k0 + lc8 * 8]);
                cp16(sB0 + so, &Bg[(size_t)row * 1024 + k0 + lc8 * 8]);
            }
            CP_COMMIT();
            CP_WAIT(1);
        } else {
            CP_WAIT(0);
        }
        __syncthreads();

        const __half* As = smA + buf * ABUF;
        const __half* Bs = smB + buf * ABUF;
#pragma unroll
        for (int kc = 0; kc < 4; kc++) {
            uint32_t af[4][4], bf[4][2];
#pragma unroll
            for (int mi = 0; mi < 4; mi++) {
                const __half* p = &As[(wm0 + mi * 16 + r) * LDH + kc * 16 + 2 * c];
                af[mi][0] = *(const uint32_t*)p;
                af[mi][1] = *(const uint32_t*)(p + 8 * LDH);
                af[mi][2] = *(const uint32_t*)(p + 8);
                af[mi][3] = *(const uint32_t*)(p + 8 * LDH + 8);
            }
#pragma unroll
            for (int nj = 0; nj < 4; nj++) {
                const __half* p = &Bs[(wn0 + nj * 8 + r) * LDH + kc * 16 + 2 * c];
                bf[nj][0] = *(const uint32_t*)p;
                bf[nj][1] = *(const uint32_t*)(p + 8);
            }
#pragma unroll
            for (int mi = 0; mi < 4; mi++)
#pragma unroll
                for (int nj = 0; nj < 4; nj++)
                    mma_f16(acc[mi][nj], af[mi], bf[nj][0], bf[nj][1]);
        }
        __syncthreads();
    }

    // Epilogue: bias + fp16 store. Q/K: [b,h][s][d]; V transposed [b,h][d][s].
#pragma unroll
    for (int nj = 0; nj < 4; nj++) {
        const int n = n0 + wn0 + nj * 8 + c * 2;
        const int h = n >> 6;
        const int d = n & 63;
        const float b0v = bias[n];
        const float b1v = bias[n + 1];
#pragma unroll
        for (int mi = 0; mi < 4; mi++) {
            const int mA = m0 + wm0 + mi * 16 + r;
            const int mB = mA + 8;
            const int bbA = mA >> 11, ssA = mA & 2047;
            const int bbB = mB >> 11, ssB = mB & 2047;
            if (sel == 2) {
                const size_t base = ((size_t)bbA * NH_ + h) * HD_;
                g_vt[(base + d)     * S_ + ssA] = __float2half(acc[mi][nj][0] + b0v);
                g_vt[(base + d + 1) * S_ + ssA] = __float2half(acc[mi][nj][1] + b1v);
                const size_t baseB = ((size_t)bbB * NH_ + h) * HD_;
                g_vt[(baseB + d)     * S_ + ssB] = __float2half(acc[mi][nj][2] + b0v);
                g_vt[(baseB + d + 1) * S_ + ssB] = __float2half(acc[mi][nj][3] + b1v);
            } else {
                __half* dst = (sel == 0) ? g_q : g_k;
                *(__half2*)&dst[(((size_t)bbA * NH_ + h) * S_ + ssA) * HD_ + d] =
                    __floats2half2_rn(acc[mi][nj][0] + b0v, acc[mi][nj][1] + b1v);
                *(__half2*)&dst[(((size_t)bbB * NH_ + h) * S_ + ssB) * HD_ + d] =
                    __floats2half2_rn(acc[mi][nj][2] + b0v, acc[mi][nj][3] + b1v);
            }
        }
    }
}

// ---------------------------------------------------------------------------
// Kernel 2: flash attention on mma.sync fp16 (fp32 accum). UNCHANGED from R4.
// ---------------------------------------------------------------------------
__global__ __launch_bounds__(128, 2)
void flash_mma(const float* __restrict__ mask, float* __restrict__ out)
{
    __shared__ __half Qs[128 * LDH];
    __shared__ __half Ks[64 * LDH];
    __shared__ __half Vts[64 * LDH];
    __shared__ float Ms[64];

    const int qt = 15 - blockIdx.x;
    const int h  = blockIdx.y;
    const int b  = blockIdx.z;
    const int tid  = threadIdx.x;
    const int w    = tid >> 5;
    const int lane = tid & 31;
    const int r = lane >> 2;
    const int c = lane & 3;

    const int q0 = qt * 128;
    const size_t hb = ((size_t)b * NH_ + h) * S_;

    {
        const __half* qg = g_q + (hb + q0) * HD_;
#pragma unroll
        for (int i = 0; i < 8; i++) {
            const int idx = i * 128 + tid;
            const int row = idx >> 3, c8 = idx & 7;
            *(uint4*)&Qs[row * LDH + c8 * 8] = *(const uint4*)&qg[row * HD_ + c8 * 8];
        }
    }
    __syncthreads();

    uint32_t qfr[2][4][4];
#pragma unroll
    for (int mi = 0; mi < 2; mi++)
#pragma unroll
        for (int kc = 0; kc < 4; kc++) {
            const __half* p = &Qs[(w * 32 + mi * 16 + r) * LDH + kc * 16 + 2 * c];
            qfr[mi][kc][0] = *(const uint32_t*)p;
            qfr[mi][kc][1] = *(const uint32_t*)(p + 8 * LDH);
            qfr[mi][kc][2] = *(const uint32_t*)(p + 8);
            qfr[mi][kc][3] = *(const uint32_t*)(p + 8 * LDH + 8);
        }

    float of[2][8][4];
#pragma unroll
    for (int mi = 0; mi < 2; mi++)
#pragma unroll
        for (int nf = 0; nf < 8; nf++)
#pragma unroll
            for (int e = 0; e < 4; e++) of[mi][nf][e] = 0.f;
    float mrun[2][2] = {{-INFINITY, -INFINITY}, {-INFINITY, -INFINITY}};
    float lsum[2][2] = {{0.f, 0.f}, {0.f, 0.f}};

    const int qr_lo = q0 + w * 32;
    const int nkt = 2 * qt + 2;

    for (int kt = 0; kt < nkt; kt++) {
        __syncthreads();
        {
            const __half* kg = g_k + (hb + kt * 64) * HD_;
            const __half* vg = g_vt + ((size_t)b * NH_ + h) * HD_ * S_ + kt * 64;
#pragma unroll
            for (int i = 0; i < 4; i++) {
                const int idx = i * 128 + tid;
                const int row = idx >> 3, c8 = idx & 7;
                *(uint4*)&Ks[row * LDH + c8 * 8]  = *(const uint4*)&kg[row * HD_ + c8 * 8];
                *(uint4*)&Vts[row * LDH + c8 * 8] = *(const uint4*)&vg[(size_t)row * S_ + c8 * 8];
            }
            if (tid < 64) Ms[tid] = mask[(size_t)b * S_ + kt * 64 + tid];
        }
        __syncthreads();

        if (kt * 64 > qr_lo + 31) continue;

        float sf[2][8][4];
#pragma unroll
        for (int mi = 0; mi < 2; mi++)
#pragma unroll
            for (int nf = 0; nf < 8; nf++)
#pragma unroll
                for (int e = 0; e < 4; e++) sf[mi][nf][e] = 0.f;
#pragma unroll
        for (int kc = 0; kc < 4; kc++)
#pragma unroll
            for (int nf = 0; nf < 8; nf++) {
                const __half* p = &Ks[(nf * 8 + r) * LDH + kc * 16 + 2 * c];
                const uint32_t b0 = *(const uint32_t*)p;
                const uint32_t b1 = *(const uint32_t*)(p + 8);
                mma_f16(sf[0][nf], qfr[0][kc], b0, b1);
                mma_f16(sf[1][nf], qfr[1][kc], b0, b1);
            }

        const bool diag = (kt * 64 + 63) > qr_lo;
        uint32_t pf[2][4][4];
#pragma unroll
        for (int mi = 0; mi < 2; mi++) {
            const int rowA = qr_lo + mi * 16 + r;
#pragma unroll
            for (int nf = 0; nf < 8; nf++) {
                const int col0 = kt * 64 + nf * 8 + 2 * c;
                const float m0v = Ms[nf * 8 + 2 * c];
                const float m1v = Ms[nf * 8 + 2 * c + 1];
                sf[mi][nf][0] = (sf[mi][nf][0] + m0v) * 0.125f;
                sf[mi][nf][1] = (sf[mi][nf][1] + m1v) * 0.125f;
                sf[mi][nf][2] = (sf[mi][nf][2] + m0v) * 0.125f;
                sf[mi][nf][3] = (sf[mi][nf][3] + m1v) * 0.125f;
                if (diag) {
                    if (col0     > rowA)     sf[mi][nf][0] = -INFINITY;
                    if (col0 + 1 > rowA)     sf[mi][nf][1] = -INFINITY;
                    if (col0     > rowA + 8) sf[mi][nf][2] = -INFINITY;
                    if (col0 + 1 > rowA + 8) sf[mi][nf][3] = -INFINITY;
                }
            }
#pragma unroll
            for (int rr = 0; rr < 2; rr++) {
                float mt = -INFINITY;
#pragma unroll
                for (int nf = 0; nf < 8; nf++)
                    mt = fmaxf(mt, fmaxf(sf[mi][nf][rr * 2], sf[mi][nf][rr * 2 + 1]));
                mt = fmaxf(mt, __shfl_xor_sync(0xffffffffu, mt, 1));
                mt = fmaxf(mt, __shfl_xor_sync(0xffffffffu, mt, 2));
                const float mn = fmaxf(mrun[mi][rr], mt);
                const float corr = __expf(mrun[mi][rr] - mn);
                mrun[mi][rr] = mn;
                float ls = 0.f;
#pragma unroll
                for (int nf = 0; nf < 8; nf++) {
                    const float p0 = __expf(sf[mi][nf][rr * 2]     - mn);
                    const float p1 = __expf(sf[mi][nf][rr * 2 + 1] - mn);
                    sf[mi][nf][rr * 2] = p0;
                    sf[mi][nf][rr * 2 + 1] = p1;
                    ls += p0 + p1;
                }
                ls += __shfl_xor_sync(0xffffffffu, ls, 1);
                ls += __shfl_xor_sync(0xffffffffu, ls, 2);
                lsum[mi][rr] = lsum[mi][rr] * corr + ls;
#pragma unroll
                for (int nf = 0; nf < 8; nf++) {
                    of[mi][nf][rr * 2]     *= corr;
                    of[mi][nf][rr * 2 + 1] *= corr;
                }
            }
#pragma unroll
            for (int kc = 0; kc < 4; kc++) {
                pf[mi][kc][0] = packh2(sf[mi][2 * kc][0],     sf[mi][2 * kc][1]);
                pf[mi][kc][1] = packh2(sf[mi][2 * kc][2],     sf[mi][2 * kc][3]);
                pf[mi][kc][2] = packh2(sf[mi][2 * kc + 1][0], sf[mi][2 * kc + 1][1]);
                pf[mi][kc][3] = packh2(sf[mi][2 * kc + 1][2], sf[mi][2 * kc + 1][3]);
            }
        }

#pragma unroll
        for (int kc = 0; kc < 4; kc++)
#pragma unroll
            for (int nd = 0; nd < 8; nd++) {
                const __half* p = &Vts[(nd * 8 + r) * LDH + kc * 16 + 2 * c];
                const uint32_t b0 = *(const uint32_t*)p;
                const uint32_t b1 = *(const uint32_t*)(p + 8);
                mma_f16(of[0][nd], pf[0][kc], b0, b1);
                mma_f16(of[1][nd], pf[1][kc], b0, b1);
            }
    }

#pragma unroll
    for (int mi = 0; mi < 2; mi++)
#pragma unroll
        for (int rr = 0; rr < 2; rr++) {
            const float inv = 1.f / lsum[mi][rr];
            const int row = q0 + w * 32 + mi * 16 + r + rr * 8;
            float* op = out + ((size_t)b * S_ + row) * H_ + h * HD_;
#pragma unroll
            for (int nf = 0; nf < 8; nf++) {
                float2 v;
                v.x = of[mi][nf][rr * 2] * inv;
                v.y = of[mi][nf][rr * 2 + 1] * inv;
                *(float2*)&op[nf * 8 + 2 * c] = v;
            }
        }
}

// ---------------------------------------------------------------------------
extern "C" void kernel_launch(void* const* d_in, const int* in_sizes, int n_in,
                              void* d_out, int out_size)
{
    const float* hs   = (const float*)d_in[0];
    const float* mask = (const float*)d_in[1];
    const float* Wq   = (const float*)d_in[2];
    const float* bq   = (const float*)d_in[3];
    const float* Wk   = (const float*)d_in[4];
    const float* bk   = (const float*)d_in[5];
    const float* Wv   = (const float*)d_in[6];
    const float* bv   = (const float*)d_in[7];
    float* out = (float*)d_out;

    const int cvt_blocks = (XH_ELEMS / 4 + 3 * (WH_ELEMS / 4) + 255) / 256;
    to_half<<<cvt_blocks, 256>>>(hs, Wq, Wk, Wv);

    const int dyn = 4 * ABUF * (int)sizeof(__half);   // 73,728 B
    static int attr_set = 0;
    if (!attr_set) {
        cudaFuncSetAttribute(qkv_h, cudaFuncAttributeMaxDynamicSharedMemorySize, dyn);
        attr_set = 1;
    }
    qkv_h<<<dim3(64, 24), 256, dyn>>>(bq, bk, bv);
    flash_mma<<<dim3(16, NH_, B_), 128>>>(mask, out);
}